// round 1
// baseline (speedup 1.0000x reference)
#include <cuda_runtime.h>
#include <math.h>

#define B_    2
#define S_    2048
#define H_    1024
#define G_    4
#define HPG_  4
#define HD_   64
#define DG_   256
#define M_    (B_ * S_)        // 4096
#define NHEADS (B_ * G_ * HPG_) // 32

// Scratch (device globals — no allocation allowed)
__device__ float g_q[M_ * H_];   // [hidx][s][hd], hidx = (b*G+g)*HPG+h
__device__ float g_k[M_ * H_];
__device__ float g_v[M_ * H_];
__device__ float g_ctx[M_ * H_]; // [b*S+s][ (g*HPG+h)*64 + hd ]

// ---------------------------------------------------------------------------
// SGEMM: C[m,n] = sum_k A[m,k] * W[n,k] + bias[n]
// M=4096, N=1024, K=1024 fixed. mode 0: row-major out. mode 1: QKV head remap.
// 128x128 tile, BK=16, 256 threads, 8x8 per-thread microtile.
// ---------------------------------------------------------------------------
__global__ void __launch_bounds__(256) sgemm_kernel(
    const float* __restrict__ A,
    const float* __restrict__ W,
    const float* __restrict__ bias,
    float* __restrict__ C,
    int mode)
{
    const int K = 1024;
    const int N = 1024;

    __shared__ float As[16][128];
    __shared__ float Bs[16][128];

    int tid = threadIdx.x;
    int tx = tid & 15;        // 0..15
    int ty = tid >> 4;        // 0..15
    int bm = blockIdx.y * 128;
    int bn = blockIdx.x * 128;

    float acc[8][8];
#pragma unroll
    for (int i = 0; i < 8; i++)
#pragma unroll
        for (int j = 0; j < 8; j++) acc[i][j] = 0.f;

    int lr = tid >> 1;           // 0..127
    int lk = (tid & 1) * 8;      // 0 or 8

    const float* Aptr = A + (size_t)(bm + lr) * K + lk;
    const float* Wptr = W + (size_t)(bn + lr) * K + lk;

    for (int k0 = 0; k0 < K; k0 += 16) {
        float4 a0 = *(const float4*)(Aptr + k0);
        float4 a1 = *(const float4*)(Aptr + k0 + 4);
        float4 b0 = *(const float4*)(Wptr + k0);
        float4 b1 = *(const float4*)(Wptr + k0 + 4);

        __syncthreads();
        As[lk + 0][lr] = a0.x; As[lk + 1][lr] = a0.y;
        As[lk + 2][lr] = a0.z; As[lk + 3][lr] = a0.w;
        As[lk + 4][lr] = a1.x; As[lk + 5][lr] = a1.y;
        As[lk + 6][lr] = a1.z; As[lk + 7][lr] = a1.w;
        Bs[lk + 0][lr] = b0.x; Bs[lk + 1][lr] = b0.y;
        Bs[lk + 2][lr] = b0.z; Bs[lk + 3][lr] = b0.w;
        Bs[lk + 4][lr] = b1.x; Bs[lk + 5][lr] = b1.y;
        Bs[lk + 6][lr] = b1.z; Bs[lk + 7][lr] = b1.w;
        __syncthreads();

#pragma unroll
        for (int kk = 0; kk < 16; kk++) {
            float4 av0 = *(const float4*)&As[kk][ty * 8];
            float4 av1 = *(const float4*)&As[kk][ty * 8 + 4];
            float4 bv0 = *(const float4*)&Bs[kk][tx * 8];
            float4 bv1 = *(const float4*)&Bs[kk][tx * 8 + 4];
            float av[8] = {av0.x, av0.y, av0.z, av0.w, av1.x, av1.y, av1.z, av1.w};
            float bv[8] = {bv0.x, bv0.y, bv0.z, bv0.w, bv1.x, bv1.y, bv1.z, bv1.w};
#pragma unroll
            for (int i = 0; i < 8; i++)
#pragma unroll
                for (int j = 0; j < 8; j++)
                    acc[i][j] = fmaf(av[i], bv[j], acc[i][j]);
        }
    }

    int row = bm + ty * 8;
    int col = bn + tx * 8;

    if (mode == 0) {
#pragma unroll
        for (int i = 0; i < 8; i++) {
            float* dst = C + (size_t)(row + i) * N + col;
#pragma unroll
            for (int j = 0; j < 8; j++)
                dst[j] = acc[i][j] + bias[col + j];
        }
    } else {
        // remap: n = g*256 + h*64 + hd ; out [hidx][s][hd]
        int g  = col >> 8;
        int h  = (col >> 6) & 3;
        int hd0 = col & 63;            // cols stay within one 64-block (col%8==0)
#pragma unroll
        for (int i = 0; i < 8; i++) {
            int m = row + i;
            int b = m >> 11;           // /2048
            int s = m & 2047;
            int hidx = (b * G_ + g) * HPG_ + h;
            float* dst = C + (size_t)hidx * (S_ * HD_) + (size_t)s * HD_ + hd0;
#pragma unroll
            for (int j = 0; j < 8; j++)
                dst[j] = acc[i][j] + bias[col + j];
        }
    }
}

// ---------------------------------------------------------------------------
// Flash-style attention, fp32, online softmax.
// Grid: (S/64, NHEADS). Block: 256 threads.
// Each block: 64 q rows of one head; loop over k in tiles of 32.
// Thread (ty=tid>>3 in 0..31, tx=tid&7): rows {ty, ty+32}; score cols tx*4+0..3;
// output dims tx*8+0..7.
// ---------------------------------------------------------------------------
__global__ void __launch_bounds__(256) attn_kernel(
    const float* __restrict__ Q,
    const float* __restrict__ Kg,
    const float* __restrict__ V,
    float* __restrict__ ctx)
{
    __shared__ float Qs[64][68];   // padded, float4-aligned rows (68*4=272=17*16)
    __shared__ float KPs[32][68];  // K tile [c][k]; reused as P^T [c][r] (r<64<68)
    __shared__ float Vs[32][64];

    int hidx = blockIdx.y;
    int qt   = blockIdx.x;
    const float* Qh = Q  + (size_t)hidx * S_ * HD_ + (size_t)qt * 64 * HD_;
    const float* Kh = Kg + (size_t)hidx * S_ * HD_;
    const float* Vh = V  + (size_t)hidx * S_ * HD_;

    int tid = threadIdx.x;
    int tx = tid & 7;    // 0..7
    int ty = tid >> 3;   // 0..31

    // load Q tile (64x64): each thread 16 floats
    {
        int r  = tid >> 2;            // 0..63
        int c0 = (tid & 3) * 16;      // 0,16,32,48
        const float4* src = (const float4*)(Qh + r * 64 + c0);
#pragma unroll
        for (int v = 0; v < 4; v++)
            *(float4*)&Qs[r][c0 + 4 * v] = src[v];
    }

    float m0 = -1e30f, m1 = -1e30f;
    float l0 = 0.f, l1 = 0.f;
    float acc0[8], acc1[8];
#pragma unroll
    for (int j = 0; j < 8; j++) { acc0[j] = 0.f; acc1[j] = 0.f; }

    const float scale = 0.125f;  // 1/sqrt(64)

    for (int kt = 0; kt < S_ / 32; kt++) {
        __syncthreads();   // protect KPs/Vs from previous iteration readers
        {
            int r  = tid >> 3;          // 0..31
            int c0 = (tid & 7) * 8;     // 0..56
            const float* ks = Kh + (size_t)(kt * 32 + r) * 64 + c0;
            const float* vs = Vh + (size_t)(kt * 32 + r) * 64 + c0;
            *(float4*)&KPs[r][c0]     = *(const float4*)ks;
            *(float4*)&KPs[r][c0 + 4] = *(const float4*)(ks + 4);
            *(float4*)&Vs[r][c0]      = *(const float4*)vs;
            *(float4*)&Vs[r][c0 + 4]  = *(const float4*)(vs + 4);
        }
        __syncthreads();

        // scores s[2][4] = Q[rows] . K[cols]
        float s00 = 0.f, s01 = 0.f, s02 = 0.f, s03 = 0.f;
        float s10 = 0.f, s11 = 0.f, s12 = 0.f, s13 = 0.f;
#pragma unroll
        for (int k = 0; k < 64; k += 4) {
            float4 q0 = *(const float4*)&Qs[ty][k];
            float4 q1 = *(const float4*)&Qs[ty + 32][k];
            float4 k0 = *(const float4*)&KPs[tx * 4 + 0][k];
            float4 k1 = *(const float4*)&KPs[tx * 4 + 1][k];
            float4 k2 = *(const float4*)&KPs[tx * 4 + 2][k];
            float4 k3 = *(const float4*)&KPs[tx * 4 + 3][k];
            s00 += q0.x*k0.x + q0.y*k0.y + q0.z*k0.z + q0.w*k0.w;
            s01 += q0.x*k1.x + q0.y*k1.y + q0.z*k1.z + q0.w*k1.w;
            s02 += q0.x*k2.x + q0.y*k2.y + q0.z*k2.z + q0.w*k2.w;
            s03 += q0.x*k3.x + q0.y*k3.y + q0.z*k3.z + q0.w*k3.w;
            s10 += q1.x*k0.x + q1.y*k0.y + q1.z*k0.z + q1.w*k0.w;
            s11 += q1.x*k1.x + q1.y*k1.y + q1.z*k1.z + q1.w*k1.w;
            s12 += q1.x*k2.x + q1.y*k2.y + q1.z*k2.z + q1.w*k2.w;
            s13 += q1.x*k3.x + q1.y*k3.y + q1.z*k3.z + q1.w*k3.w;
        }
        s00 *= scale; s01 *= scale; s02 *= scale; s03 *= scale;
        s10 *= scale; s11 *= scale; s12 *= scale; s13 *= scale;

        // row max over tile (within 8-lane tx group)
        float tm0 = fmaxf(fmaxf(s00, s01), fmaxf(s02, s03));
        float tm1 = fmaxf(fmaxf(s10, s11), fmaxf(s12, s13));
#pragma unroll
        for (int off = 1; off < 8; off <<= 1) {
            tm0 = fmaxf(tm0, __shfl_xor_sync(0xFFFFFFFFu, tm0, off));
            tm1 = fmaxf(tm1, __shfl_xor_sync(0xFFFFFFFFu, tm1, off));
        }
        float mn0 = fmaxf(m0, tm0);
        float mn1 = fmaxf(m1, tm1);
        float sc0 = __expf(m0 - mn0);
        float sc1 = __expf(m1 - mn1);

        float p00 = __expf(s00 - mn0), p01 = __expf(s01 - mn0);
        float p02 = __expf(s02 - mn0), p03 = __expf(s03 - mn0);
        float p10 = __expf(s10 - mn1), p11 = __expf(s11 - mn1);
        float p12 = __expf(s12 - mn1), p13 = __expf(s13 - mn1);

        float rs0 = p00 + p01 + p02 + p03;
        float rs1 = p10 + p11 + p12 + p13;
#pragma unroll
        for (int off = 1; off < 8; off <<= 1) {
            rs0 += __shfl_xor_sync(0xFFFFFFFFu, rs0, off);
            rs1 += __shfl_xor_sync(0xFFFFFFFFu, rs1, off);
        }
        l0 = l0 * sc0 + rs0;
        l1 = l1 * sc1 + rs1;
        m0 = mn0; m1 = mn1;
#pragma unroll
        for (int j = 0; j < 8; j++) { acc0[j] *= sc0; acc1[j] *= sc1; }

        __syncthreads();   // everyone done reading K tile before overwriting as P
        // store P transposed: KPs[c][r]
        KPs[tx * 4 + 0][ty]      = p00;
        KPs[tx * 4 + 1][ty]      = p01;
        KPs[tx * 4 + 2][ty]      = p02;
        KPs[tx * 4 + 3][ty]      = p03;
        KPs[tx * 4 + 0][ty + 32] = p10;
        KPs[tx * 4 + 1][ty + 32] = p11;
        KPs[tx * 4 + 2][ty + 32] = p12;
        KPs[tx * 4 + 3][ty + 32] = p13;
        __syncthreads();

        // acc += P @ V
#pragma unroll 4
        for (int c = 0; c < 32; c++) {
            float p0 = KPs[c][ty];
            float p1 = KPs[c][ty + 32];
            float4 v0 = *(const float4*)&Vs[c][tx * 8];
            float4 v1 = *(const float4*)&Vs[c][tx * 8 + 4];
            acc0[0] = fmaf(p0, v0.x, acc0[0]);
            acc0[1] = fmaf(p0, v0.y, acc0[1]);
            acc0[2] = fmaf(p0, v0.z, acc0[2]);
            acc0[3] = fmaf(p0, v0.w, acc0[3]);
            acc0[4] = fmaf(p0, v1.x, acc0[4]);
            acc0[5] = fmaf(p0, v1.y, acc0[5]);
            acc0[6] = fmaf(p0, v1.z, acc0[6]);
            acc0[7] = fmaf(p0, v1.w, acc0[7]);
            acc1[0] = fmaf(p1, v0.x, acc1[0]);
            acc1[1] = fmaf(p1, v0.y, acc1[1]);
            acc1[2] = fmaf(p1, v0.z, acc1[2]);
            acc1[3] = fmaf(p1, v0.w, acc1[3]);
            acc1[4] = fmaf(p1, v1.x, acc1[4]);
            acc1[5] = fmaf(p1, v1.y, acc1[5]);
            acc1[6] = fmaf(p1, v1.z, acc1[6]);
            acc1[7] = fmaf(p1, v1.w, acc1[7]);
        }
    }

    // write ctx: [(b*S + s)][ gh*64 + d ], gh = g*HPG+h = hidx & 15, b = hidx>>4
    int b  = hidx >> 4;
    int gh = hidx & 15;
    float inv0 = 1.f / l0;
    float inv1 = 1.f / l1;
    size_t base = ((size_t)b * S_ + (size_t)qt * 64) * H_ + gh * 64 + tx * 8;
    float4 o0a = {acc0[0]*inv0, acc0[1]*inv0, acc0[2]*inv0, acc0[3]*inv0};
    float4 o0b = {acc0[4]*inv0, acc0[5]*inv0, acc0[6]*inv0, acc0[7]*inv0};
    float4 o1a = {acc1[0]*inv1, acc1[1]*inv1, acc1[2]*inv1, acc1[3]*inv1};
    float4 o1b = {acc1[4]*inv1, acc1[5]*inv1, acc1[6]*inv1, acc1[7]*inv1};
    *(float4*)(ctx + base + (size_t)ty * H_)            = o0a;
    *(float4*)(ctx + base + (size_t)ty * H_ + 4)        = o0b;
    *(float4*)(ctx + base + (size_t)(ty + 32) * H_)     = o1a;
    *(float4*)(ctx + base + (size_t)(ty + 32) * H_ + 4) = o1b;
}

// ---------------------------------------------------------------------------
extern "C" void kernel_launch(void* const* d_in, const int* in_sizes, int n_in,
                              void* d_out, int out_size)
{
    const float* x  = (const float*)d_in[0];
    const float* Wq = (const float*)d_in[1];
    const float* bq = (const float*)d_in[2];
    const float* Wk = (const float*)d_in[3];
    const float* bk = (const float*)d_in[4];
    const float* Wv = (const float*)d_in[5];
    const float* bv = (const float*)d_in[6];
    const float* Wo = (const float*)d_in[7];
    const float* bo = (const float*)d_in[8];
    float* out = (float*)d_out;

    float *q, *k, *v, *ctx;
    cudaGetSymbolAddress((void**)&q,   g_q);
    cudaGetSymbolAddress((void**)&k,   g_k);
    cudaGetSymbolAddress((void**)&v,   g_v);
    cudaGetSymbolAddress((void**)&ctx, g_ctx);

    dim3 ggrid(8, 32);   // N/128, M/128
    dim3 gblk(256);

    sgemm_kernel<<<ggrid, gblk>>>(x, Wq, bq, q, 1);
    sgemm_kernel<<<ggrid, gblk>>>(x, Wk, bk, k, 1);
    sgemm_kernel<<<ggrid, gblk>>>(x, Wv, bv, v, 1);

    attn_kernel<<<dim3(S_ / 64, NHEADS), 256>>>(q, k, v, ctx);

    sgemm_kernel<<<ggrid, gblk>>>(ctx, Wo, bo, out, 0);
}

// round 2
// speedup vs baseline: 2.1204x; 2.1204x over previous
#include <cuda_runtime.h>
#include <math.h>

#define B_    2
#define S_    2048
#define H_    1024
#define G_    4
#define HPG_  4
#define HD_   64
#define DG_   256
#define M_    (B_ * S_)          // 4096
#define NHEADS (B_ * G_ * HPG_)  // 32

typedef unsigned long long ull;

// Scratch (device globals — no allocation allowed)
__device__ float g_q[M_ * H_];   // [hidx][s][hd], hidx = (b*G+g)*HPG+h
__device__ float g_k[M_ * H_];
__device__ float g_v[M_ * H_];
__device__ float g_ctx[M_ * H_]; // [b*S+s][ (g*HPG+h)*64 + hd ]

// ---- packed f32x2 helpers (Blackwell FFMA2 path, PTX-only) --------------
__device__ __forceinline__ void fma2(ull& d, ull a, ull b) {
    asm("fma.rn.f32x2 %0, %1, %2, %0;" : "+l"(d) : "l"(a), "l"(b));
}
__device__ __forceinline__ void mul2(ull& d, ull a) {
    asm("mul.rn.f32x2 %0, %0, %1;" : "+l"(d) : "l"(a));
}
__device__ __forceinline__ ull pack2(float x) {
    ull r; asm("mov.b64 %0, {%1, %1};" : "=l"(r) : "f"(x)); return r;
}
__device__ __forceinline__ float2 unpack2(ull v) {
    float2 r; asm("mov.b64 {%0, %1}, %2;" : "=f"(r.x), "=f"(r.y) : "l"(v)); return r;
}

// ---------------------------------------------------------------------------
// SGEMM: C[m,n] = sum_k A[m,k]*W[n,k] + bias[n].  M=4096,N=1024,K=1024.
// 128x128 tile, BK=16, 256 threads, 8x8 microtile via f32x2, reg prefetch.
// mode 0: row-major out. mode 1: QKV head remap.
// ---------------------------------------------------------------------------
__global__ void __launch_bounds__(256) sgemm_kernel(
    const float* __restrict__ A,
    const float* __restrict__ W,
    const float* __restrict__ bias,
    float* __restrict__ C,
    int mode)
{
    const int K = 1024;
    const int N = 1024;

    __shared__ float As[16][128];
    __shared__ float Bs[16][128];

    int tid = threadIdx.x;
    int tx = tid & 15;
    int ty = tid >> 4;
    int bm = blockIdx.y * 128;
    int bn = blockIdx.x * 128;

    ull acc2[8][4];
#pragma unroll
    for (int i = 0; i < 8; i++)
#pragma unroll
        for (int j = 0; j < 4; j++) acc2[i][j] = 0ull;

    int lr = tid >> 1;
    int lk = (tid & 1) * 8;

    const float* Aptr = A + (size_t)(bm + lr) * K + lk;
    const float* Wptr = W + (size_t)(bn + lr) * K + lk;

    float4 a0 = *(const float4*)(Aptr);
    float4 a1 = *(const float4*)(Aptr + 4);
    float4 b0 = *(const float4*)(Wptr);
    float4 b1 = *(const float4*)(Wptr + 4);

    for (int k0 = 0; k0 < K; k0 += 16) {
        __syncthreads();
        As[lk + 0][lr] = a0.x; As[lk + 1][lr] = a0.y;
        As[lk + 2][lr] = a0.z; As[lk + 3][lr] = a0.w;
        As[lk + 4][lr] = a1.x; As[lk + 5][lr] = a1.y;
        As[lk + 6][lr] = a1.z; As[lk + 7][lr] = a1.w;
        Bs[lk + 0][lr] = b0.x; Bs[lk + 1][lr] = b0.y;
        Bs[lk + 2][lr] = b0.z; Bs[lk + 3][lr] = b0.w;
        Bs[lk + 4][lr] = b1.x; Bs[lk + 5][lr] = b1.y;
        Bs[lk + 6][lr] = b1.z; Bs[lk + 7][lr] = b1.w;
        __syncthreads();

        if (k0 + 16 < K) {  // prefetch next K-slab while computing this one
            a0 = *(const float4*)(Aptr + k0 + 16);
            a1 = *(const float4*)(Aptr + k0 + 20);
            b0 = *(const float4*)(Wptr + k0 + 16);
            b1 = *(const float4*)(Wptr + k0 + 20);
        }

#pragma unroll
        for (int kk = 0; kk < 16; kk++) {
            float4 av0 = *(const float4*)&As[kk][ty * 8];
            float4 av1 = *(const float4*)&As[kk][ty * 8 + 4];
            ulonglong2 bu0 = *(const ulonglong2*)&Bs[kk][tx * 8];
            ulonglong2 bu1 = *(const ulonglong2*)&Bs[kk][tx * 8 + 4];
            ull du[8];
            du[0] = pack2(av0.x); du[1] = pack2(av0.y);
            du[2] = pack2(av0.z); du[3] = pack2(av0.w);
            du[4] = pack2(av1.x); du[5] = pack2(av1.y);
            du[6] = pack2(av1.z); du[7] = pack2(av1.w);
#pragma unroll
            for (int i = 0; i < 8; i++) {
                fma2(acc2[i][0], du[i], bu0.x);
                fma2(acc2[i][1], du[i], bu0.y);
                fma2(acc2[i][2], du[i], bu1.x);
                fma2(acc2[i][3], du[i], bu1.y);
            }
        }
    }

    int row = bm + ty * 8;
    int col = bn + tx * 8;

    float cvals[8][8];
#pragma unroll
    for (int i = 0; i < 8; i++)
#pragma unroll
        for (int j = 0; j < 4; j++) {
            float2 u = unpack2(acc2[i][j]);
            cvals[i][2 * j]     = u.x;
            cvals[i][2 * j + 1] = u.y;
        }

    if (mode == 0) {
#pragma unroll
        for (int i = 0; i < 8; i++) {
            float* dst = C + (size_t)(row + i) * N + col;
#pragma unroll
            for (int j = 0; j < 8; j++)
                dst[j] = cvals[i][j] + bias[col + j];
        }
    } else {
        int g   = col >> 8;
        int h   = (col >> 6) & 3;
        int hd0 = col & 63;
#pragma unroll
        for (int i = 0; i < 8; i++) {
            int m = row + i;
            int b = m >> 11;
            int s = m & 2047;
            int hidx = (b * G_ + g) * HPG_ + h;
            float* dst = C + (size_t)hidx * (S_ * HD_) + (size_t)s * HD_ + hd0;
#pragma unroll
            for (int j = 0; j < 8; j++)
                dst[j] = cvals[i][j] + bias[col + j];
        }
    }
}

// ---------------------------------------------------------------------------
// Flash attention, fp32, f32x2 math. 64 q-rows per block, 64-kv tiles.
// 128 threads: tx=tid&15 (score cols tx*4.., ctx dims tx*4..),
//              ty=tid>>4 (rows ty*8..+7).
// Smem: Qs[d][r] (transposed), KP = Ks[d][c] then Ps[r][c], Vs[c][d]. 48KB.
// ---------------------------------------------------------------------------
__global__ void __launch_bounds__(128) attn_kernel(
    const float* __restrict__ Q,
    const float* __restrict__ Kg,
    const float* __restrict__ V,
    float* __restrict__ ctx)
{
    __shared__ float Qs[64][64];   // [d][r]
    __shared__ float KP[64][64];   // Ks[d][c]  /  Ps[r][c]
    __shared__ float Vs[64][64];   // [c][d]

    int hidx = blockIdx.y;
    int qt   = blockIdx.x;
    const float* Qh = Q  + ((size_t)hidx * S_ + (size_t)qt * 64) * HD_;
    const float* Kh = Kg + (size_t)hidx * S_ * HD_;
    const float* Vh = V  + (size_t)hidx * S_ * HD_;

    int tid = threadIdx.x;
    int tx = tid & 15;
    int ty = tid >> 4;

    // ---- load Q transposed (once) ----
    {
        int r  = tid >> 1;
        int d0 = (tid & 1) * 32;
        const float4* src = (const float4*)(Qh + r * 64 + d0);
#pragma unroll
        for (int w = 0; w < 8; w++) {
            float4 t = src[w];
            Qs[d0 + 4 * w + 0][r] = t.x;
            Qs[d0 + 4 * w + 1][r] = t.y;
            Qs[d0 + 4 * w + 2][r] = t.z;
            Qs[d0 + 4 * w + 3][r] = t.w;
        }
    }

    ull acc2[8][2];
    float m[8], l[8];
#pragma unroll
    for (int i = 0; i < 8; i++) {
        acc2[i][0] = 0ull; acc2[i][1] = 0ull;
        m[i] = -1e30f; l[i] = 0.f;
    }

    const float SC = 0.18033688011112042f;  // (1/sqrt(64)) * log2(e)

    for (int kt = 0; kt < S_ / 64; kt++) {
        __syncthreads();   // previous tile's PV done with KP/Vs
        // ---- load K transposed + V natural ----
        {
            int c  = tid >> 1;
            int d0 = (tid & 1) * 32;
            const float4* ks = (const float4*)(Kh + ((size_t)kt * 64 + c) * 64 + d0);
            const float4* vs = (const float4*)(Vh + ((size_t)kt * 64 + c) * 64 + d0);
#pragma unroll
            for (int w = 0; w < 8; w++) {
                float4 t = ks[w];
                KP[d0 + 4 * w + 0][c] = t.x;
                KP[d0 + 4 * w + 1][c] = t.y;
                KP[d0 + 4 * w + 2][c] = t.z;
                KP[d0 + 4 * w + 3][c] = t.w;
                *(float4*)&Vs[c][d0 + 4 * w] = vs[w];
            }
        }
        __syncthreads();

        // ---- scores: S = Q . K^T (8 rows x 4 cols per thread, f32x2) ----
        ull s2[8][2];
#pragma unroll
        for (int i = 0; i < 8; i++) { s2[i][0] = 0ull; s2[i][1] = 0ull; }

#pragma unroll 8
        for (int d = 0; d < 64; d++) {
            float4 qa0 = *(const float4*)&Qs[d][ty * 8];
            float4 qa1 = *(const float4*)&Qs[d][ty * 8 + 4];
            ulonglong2 kb = *(const ulonglong2*)&KP[d][tx * 4];
            ull du[8];
            du[0] = pack2(qa0.x); du[1] = pack2(qa0.y);
            du[2] = pack2(qa0.z); du[3] = pack2(qa0.w);
            du[4] = pack2(qa1.x); du[5] = pack2(qa1.y);
            du[6] = pack2(qa1.z); du[7] = pack2(qa1.w);
#pragma unroll
            for (int i = 0; i < 8; i++) {
                fma2(s2[i][0], du[i], kb.x);
                fma2(s2[i][1], du[i], kb.y);
            }
        }

        // ---- online softmax ----
        float p[8][4];
#pragma unroll
        for (int i = 0; i < 8; i++) {
            float2 u0 = unpack2(s2[i][0]);
            float2 u1 = unpack2(s2[i][1]);
            float t0 = u0.x * SC, t1 = u0.y * SC, t2 = u1.x * SC, t3 = u1.y * SC;
            float rm = fmaxf(fmaxf(t0, t1), fmaxf(t2, t3));
#pragma unroll
            for (int off = 1; off < 16; off <<= 1)
                rm = fmaxf(rm, __shfl_xor_sync(0xFFFFFFFFu, rm, off));
            float nm = fmaxf(m[i], rm);
            float scf = exp2f(m[i] - nm);
            m[i] = nm;
            p[i][0] = exp2f(t0 - nm);
            p[i][1] = exp2f(t1 - nm);
            p[i][2] = exp2f(t2 - nm);
            p[i][3] = exp2f(t3 - nm);
            float rs = (p[i][0] + p[i][1]) + (p[i][2] + p[i][3]);
#pragma unroll
            for (int off = 1; off < 16; off <<= 1)
                rs += __shfl_xor_sync(0xFFFFFFFFu, rs, off);
            l[i] = l[i] * scf + rs;
            ull sd = pack2(scf);
            mul2(acc2[i][0], sd);
            mul2(acc2[i][1], sd);
        }

        __syncthreads();   // all threads done reading Ks before P overwrite
#pragma unroll
        for (int i = 0; i < 8; i++)
            *(float4*)&KP[ty * 8 + i][tx * 4] =
                make_float4(p[i][0], p[i][1], p[i][2], p[i][3]);
        __syncthreads();

        // ---- PV: acc += P @ V (f32x2, 4 kv cols per step) ----
#pragma unroll 4
        for (int c0 = 0; c0 < 64; c0 += 4) {
            float pr[8][4];
#pragma unroll
            for (int i = 0; i < 8; i++)
                *(float4*)pr[i] = *(const float4*)&KP[ty * 8 + i][c0];
            ulonglong2 v0 = *(const ulonglong2*)&Vs[c0 + 0][tx * 4];
            ulonglong2 v1 = *(const ulonglong2*)&Vs[c0 + 1][tx * 4];
            ulonglong2 v2 = *(const ulonglong2*)&Vs[c0 + 2][tx * 4];
            ulonglong2 v3 = *(const ulonglong2*)&Vs[c0 + 3][tx * 4];
#pragma unroll
            for (int i = 0; i < 8; i++) {
                ull pd;
                pd = pack2(pr[i][0]); fma2(acc2[i][0], pd, v0.x); fma2(acc2[i][1], pd, v0.y);
                pd = pack2(pr[i][1]); fma2(acc2[i][0], pd, v1.x); fma2(acc2[i][1], pd, v1.y);
                pd = pack2(pr[i][2]); fma2(acc2[i][0], pd, v2.x); fma2(acc2[i][1], pd, v2.y);
                pd = pack2(pr[i][3]); fma2(acc2[i][0], pd, v3.x); fma2(acc2[i][1], pd, v3.y);
            }
        }
    }

    // ---- epilogue: ctx[(b*S+s)][gh*64 + d] ----
    int b  = hidx >> 4;
    int gh = hidx & 15;
#pragma unroll
    for (int i = 0; i < 8; i++) {
        float inv = 1.f / l[i];
        float2 u0 = unpack2(acc2[i][0]);
        float2 u1 = unpack2(acc2[i][1]);
        float4 o = make_float4(u0.x * inv, u0.y * inv, u1.x * inv, u1.y * inv);
        size_t row = (size_t)b * S_ + (size_t)qt * 64 + ty * 8 + i;
        *(float4*)(ctx + row * H_ + gh * 64 + tx * 4) = o;
    }
}

// ---------------------------------------------------------------------------
extern "C" void kernel_launch(void* const* d_in, const int* in_sizes, int n_in,
                              void* d_out, int out_size)
{
    const float* x  = (const float*)d_in[0];
    const float* Wq = (const float*)d_in[1];
    const float* bq = (const float*)d_in[2];
    const float* Wk = (const float*)d_in[3];
    const float* bk = (const float*)d_in[4];
    const float* Wv = (const float*)d_in[5];
    const float* bv = (const float*)d_in[6];
    const float* Wo = (const float*)d_in[7];
    const float* bo = (const float*)d_in[8];
    float* out = (float*)d_out;

    float *q, *k, *v, *ctx;
    cudaGetSymbolAddress((void**)&q,   g_q);
    cudaGetSymbolAddress((void**)&k,   g_k);
    cudaGetSymbolAddress((void**)&v,   g_v);
    cudaGetSymbolAddress((void**)&ctx, g_ctx);

    dim3 ggrid(8, 32);
    dim3 gblk(256);

    sgemm_kernel<<<ggrid, gblk>>>(x, Wq, bq, q, 1);
    sgemm_kernel<<<ggrid, gblk>>>(x, Wk, bk, k, 1);
    sgemm_kernel<<<ggrid, gblk>>>(x, Wv, bv, v, 1);

    attn_kernel<<<dim3(S_ / 64, NHEADS), 128>>>(q, k, v, ctx);

    sgemm_kernel<<<ggrid, gblk>>>(ctx, Wo, bo, out, 0);
}

// round 4
// speedup vs baseline: 2.9392x; 1.3862x over previous
#include <cuda_runtime.h>
#include <cuda_bf16.h>
#include <stdint.h>
#include <math.h>

#define B_    2
#define S_    2048
#define H_    1024
#define G_    4
#define HPG_  4
#define HD_   64
#define M_    (B_ * S_)          // 4096
#define NHEADS (B_ * G_ * HPG_)  // 32

typedef unsigned long long ull;

// ---------------- scratch (device globals; no allocation allowed) ----------
__device__ float g_q[M_ * H_];
__device__ float g_k[M_ * H_];
__device__ float g_v[M_ * H_];
__device__ float g_ctx[M_ * H_];
__device__ __nv_bfloat16 g_ahi[M_ * H_];     // activation hi (x, later ctx)
__device__ __nv_bfloat16 g_alo[M_ * H_];     // activation lo
__device__ __nv_bfloat16 g_whi[4 * H_ * H_]; // Wq|Wk|Wv|Wo hi
__device__ __nv_bfloat16 g_wlo[4 * H_ * H_]; // lo

// ---------------- PTX helpers (all plain sm_80+/sm_90 features) -------------
__device__ __forceinline__ uint32_t smem_u32(const void* p) {
    uint32_t a;
    asm("{ .reg .u64 t; cvta.to.shared.u64 t, %1; cvt.u32.u64 %0, t; }" : "=r"(a) : "l"(p));
    return a;
}
__device__ __forceinline__ void cp16(uint32_t dst, const void* src) {
    asm volatile("cp.async.cg.shared.global [%0], [%1], 16;" :: "r"(dst), "l"(src) : "memory");
}
#define LDSM4(r, a) \
    asm volatile("ldmatrix.sync.aligned.m8n8.x4.shared.b16 {%0,%1,%2,%3}, [%4];" \
        : "=r"((r)[0]), "=r"((r)[1]), "=r"((r)[2]), "=r"((r)[3]) : "r"(a))
#define MMA_BF16(d, a, b0, b1) \
    asm volatile("mma.sync.aligned.m16n8k16.row.col.f32.bf16.bf16.f32 " \
        "{%0,%1,%2,%3}, {%4,%5,%6,%7}, {%8,%9}, {%0,%1,%2,%3};" \
        : "+f"((d)[0]), "+f"((d)[1]), "+f"((d)[2]), "+f"((d)[3]) \
        : "r"((a)[0]), "r"((a)[1]), "r"((a)[2]), "r"((a)[3]), "r"(b0), "r"(b1))

// ---- packed f32x2 helpers (attention) --------------------------------------
__device__ __forceinline__ void fma2(ull& d, ull a, ull b) {
    asm("fma.rn.f32x2 %0, %1, %2, %0;" : "+l"(d) : "l"(a), "l"(b));
}
__device__ __forceinline__ void mul2(ull& d, ull a) {
    asm("mul.rn.f32x2 %0, %0, %1;" : "+l"(d) : "l"(a));
}
__device__ __forceinline__ ull pack2(float x) {
    ull r; asm("mov.b64 %0, {%1, %1};" : "=l"(r) : "f"(x)); return r;
}
__device__ __forceinline__ float2 unpack2(ull v) {
    float2 r; asm("mov.b64 {%0, %1}, %2;" : "=f"(r.x), "=f"(r.y) : "l"(v)); return r;
}

// ---------------------------------------------------------------------------
// split fp32 -> bf16 hi + bf16 lo
// ---------------------------------------------------------------------------
__global__ void __launch_bounds__(256) split_kernel(
    const float* __restrict__ src,
    __nv_bfloat16* __restrict__ hi,
    __nv_bfloat16* __restrict__ lo,
    int n)
{
    int i = (blockIdx.x * 256 + threadIdx.x) * 4;
    if (i >= n) return;
    float4 v = *(const float4*)(src + i);
    __nv_bfloat16 h0 = __float2bfloat16_rn(v.x);
    __nv_bfloat16 h1 = __float2bfloat16_rn(v.y);
    __nv_bfloat16 h2 = __float2bfloat16_rn(v.z);
    __nv_bfloat16 h3 = __float2bfloat16_rn(v.w);
    __nv_bfloat16 l0 = __float2bfloat16_rn(v.x - __bfloat162float(h0));
    __nv_bfloat16 l1 = __float2bfloat16_rn(v.y - __bfloat162float(h1));
    __nv_bfloat16 l2 = __float2bfloat16_rn(v.z - __bfloat162float(h2));
    __nv_bfloat16 l3 = __float2bfloat16_rn(v.w - __bfloat162float(h3));
    __nv_bfloat162 ha; ha.x = h0; ha.y = h1;
    __nv_bfloat162 hb; hb.x = h2; hb.y = h3;
    __nv_bfloat162 la; la.x = l0; la.y = l1;
    __nv_bfloat162 lb; lb.x = l2; lb.y = l3;
    *(__nv_bfloat162*)(hi + i)     = ha;
    *(__nv_bfloat162*)(hi + i + 2) = hb;
    *(__nv_bfloat162*)(lo + i)     = la;
    *(__nv_bfloat162*)(lo + i + 2) = lb;
}

// ---------------------------------------------------------------------------
// HMMA split-bf16 GEMM: C[m,n] = sum_k A[m,k]*W[n,k] + bias[n]
// M=4096, N=1024, K=1024. CTA tile 128x128, BK=16, 2-stage cp.async pipeline.
// 8 warps (4 m x 2 n), each warp 32x64 via mma.m16n8k16 bf16, 3 split terms.
// mode 0: row-major out. mode 1: QKV head remap.
// Smem stage (16KB): Ah[0,4K) Al[4K,8K) Wh[8K,12K) Wl[12K,16K); rows 32B,
// 16B chunk q of row r stored at r*32 + ((q ^ ((r>>2)&1))*16)  (conflict-free).
// ---------------------------------------------------------------------------
__global__ void __launch_bounds__(256, 1) tc_gemm(
    const __nv_bfloat16* __restrict__ Ahi, const __nv_bfloat16* __restrict__ Alo,
    const __nv_bfloat16* __restrict__ Whi, const __nv_bfloat16* __restrict__ Wlo,
    const float* __restrict__ bias, float* __restrict__ C, int mode)
{
    __shared__ __align__(128) char sm[2][16384];
    const int K = 1024;
    int tid  = threadIdx.x;
    int wid  = tid >> 5, lane = tid & 31;
    int warp_m = wid & 3, warp_n = wid >> 2;
    int bm = blockIdx.y * 128, bn = blockIdx.x * 128;
    uint32_t sbase = smem_u32(sm);

    // -- cp.async thread mapping: row lr = tid/2, chunk lq = tid&1 --
    int lr = tid >> 1, lq = tid & 1;
    uint32_t sw_off = (uint32_t)lr * 32 + (uint32_t)((lq ^ ((lr >> 2) & 1)) << 4);
    const char* gAh = (const char*)(Ahi + (size_t)(bm + lr) * K) + lq * 16;
    const char* gAl = (const char*)(Alo + (size_t)(bm + lr) * K) + lq * 16;
    const char* gWh = (const char*)(Whi + (size_t)(bn + lr) * K) + lq * 16;
    const char* gWl = (const char*)(Wlo + (size_t)(bn + lr) * K) + lq * 16;

#define ISSUE(slab) do { \
    uint32_t st_ = sbase + (uint32_t)(((slab) & 1) * 16384); \
    size_t go_ = (size_t)(slab) * 32; \
    cp16(st_ + 0     + sw_off, gAh + go_); \
    cp16(st_ + 4096  + sw_off, gAl + go_); \
    cp16(st_ + 8192  + sw_off, gWh + go_); \
    cp16(st_ + 12288 + sw_off, gWl + go_); \
    asm volatile("cp.async.commit_group;" ::: "memory"); \
} while (0)

    // -- ldmatrix lane offsets (precomputed; swizzle bit invariant to +16 rows) --
    int mat = lane >> 3, l7 = lane & 7;
    int aR = warp_m * 32 + (mat & 1) * 8 + l7;   // + mt*16 at use
    int aQ = mat >> 1;
    int bR = warp_n * 64 + (mat >> 1) * 8 + l7;  // + g4*16 at use
    int bQ = mat & 1;
    uint32_t aSw = (uint32_t)aR * 32 + (uint32_t)((aQ ^ ((aR >> 2) & 1)) << 4);
    uint32_t bSw = (uint32_t)bR * 32 + (uint32_t)((bQ ^ ((bR >> 2) & 1)) << 4);

    float acc[2][8][4];
#pragma unroll
    for (int mt = 0; mt < 2; mt++)
#pragma unroll
        for (int nt = 0; nt < 8; nt++)
#pragma unroll
            for (int j = 0; j < 4; j++) acc[mt][nt][j] = 0.f;

    ISSUE(0);
    for (int c = 0; c < 64; c++) {
        if (c + 1 < 64) {
            ISSUE(c + 1);
            asm volatile("cp.async.wait_group 1;" ::: "memory");
        } else {
            asm volatile("cp.async.wait_group 0;" ::: "memory");
        }
        __syncthreads();
        uint32_t st = sbase + (uint32_t)((c & 1) * 16384);

        uint32_t Ah[2][4], Al[2][4], Bh[4][4], Bl[4][4];
        LDSM4(Ah[0], st + aSw);
        LDSM4(Ah[1], st + aSw + 512);
        LDSM4(Al[0], st + 4096 + aSw);
        LDSM4(Al[1], st + 4096 + aSw + 512);
#pragma unroll
        for (int g4 = 0; g4 < 4; g4++) {
            LDSM4(Bh[g4], st + 8192  + bSw + g4 * 512);
            LDSM4(Bl[g4], st + 12288 + bSw + g4 * 512);
        }

#pragma unroll
        for (int mt = 0; mt < 2; mt++)
#pragma unroll
            for (int nt = 0; nt < 8; nt++) {
                uint32_t bh0 = Bh[nt >> 1][(nt & 1) * 2];
                uint32_t bh1 = Bh[nt >> 1][(nt & 1) * 2 + 1];
                uint32_t bl0 = Bl[nt >> 1][(nt & 1) * 2];
                uint32_t bl1 = Bl[nt >> 1][(nt & 1) * 2 + 1];
                MMA_BF16(acc[mt][nt], Ah[mt], bh0, bh1);  // hi*hi
                MMA_BF16(acc[mt][nt], Al[mt], bh0, bh1);  // lo*hi
                MMA_BF16(acc[mt][nt], Ah[mt], bl0, bl1);  // hi*lo
            }
        __syncthreads();
    }
#undef ISSUE

    // -- epilogue: D frag d0:(g,2t) d1:(g,2t+1) d2:(g+8,2t) d3:(g+8,2t+1) --
    int g = lane >> 2, t = lane & 3;
#pragma unroll
    for (int mt = 0; mt < 2; mt++) {
        int row0 = bm + warp_m * 32 + mt * 16 + g;
#pragma unroll
        for (int nt = 0; nt < 8; nt++) {
            int col = bn + warp_n * 64 + nt * 8 + 2 * t;
            float2 bv = *(const float2*)(bias + col);
            float2 vlo = make_float2(acc[mt][nt][0] + bv.x, acc[mt][nt][1] + bv.y);
            float2 vhi = make_float2(acc[mt][nt][2] + bv.x, acc[mt][nt][3] + bv.y);
            if (mode == 0) {
                *(float2*)(C + (size_t)row0 * H_ + col)       = vlo;
                *(float2*)(C + (size_t)(row0 + 8) * H_ + col) = vhi;
            } else {
                // n = g*256 + h*64 + hd -> out[hidx][s][hd]
                int gph = col >> 6;
                int hd0 = col & 63;
                int b0 = row0 >> 11, s0 = row0 & 2047;
                int b1 = (row0 + 8) >> 11, s1 = (row0 + 8) & 2047;
                *(float2*)(C + (size_t)(b0 * 16 + gph) * (S_ * HD_) + (size_t)s0 * HD_ + hd0) = vlo;
                *(float2*)(C + (size_t)(b1 * 16 + gph) * (S_ * HD_) + (size_t)s1 * HD_ + hd0) = vhi;
            }
        }
    }
}

// ---------------------------------------------------------------------------
// Flash attention, fp32, f32x2 math (unchanged from R2 — 997us, L1-bound).
// ---------------------------------------------------------------------------
__global__ void __launch_bounds__(128) attn_kernel(
    const float* __restrict__ Q,
    const float* __restrict__ Kg,
    const float* __restrict__ V,
    float* __restrict__ ctx)
{
    __shared__ float Qs[64][64];
    __shared__ float KP[64][64];
    __shared__ float Vs[64][64];

    int hidx = blockIdx.y;
    int qt   = blockIdx.x;
    const float* Qh = Q  + ((size_t)hidx * S_ + (size_t)qt * 64) * HD_;
    const float* Kh = Kg + (size_t)hidx * S_ * HD_;
    const float* Vh = V  + (size_t)hidx * S_ * HD_;

    int tid = threadIdx.x;
    int tx = tid & 15;
    int ty = tid >> 4;

    {
        int r  = tid >> 1;
        int d0 = (tid & 1) * 32;
        const float4* src = (const float4*)(Qh + r * 64 + d0);
#pragma unroll
        for (int w = 0; w < 8; w++) {
            float4 t = src[w];
            Qs[d0 + 4 * w + 0][r] = t.x;
            Qs[d0 + 4 * w + 1][r] = t.y;
            Qs[d0 + 4 * w + 2][r] = t.z;
            Qs[d0 + 4 * w + 3][r] = t.w;
        }
    }

    ull acc2[8][2];
    float m[8], l[8];
#pragma unroll
    for (int i = 0; i < 8; i++) {
        acc2[i][0] = 0ull; acc2[i][1] = 0ull;
        m[i] = -1e30f; l[i] = 0.f;
    }

    const float SC = 0.18033688011112042f;  // (1/8) * log2(e)

    for (int kt = 0; kt < S_ / 64; kt++) {
        __syncthreads();
        {
            int c  = tid >> 1;
            int d0 = (tid & 1) * 32;
            const float4* ks = (const float4*)(Kh + ((size_t)kt * 64 + c) * 64 + d0);
            const float4* vs = (const float4*)(Vh + ((size_t)kt * 64 + c) * 64 + d0);
#pragma unroll
            for (int w = 0; w < 8; w++) {
                float4 t = ks[w];
                KP[d0 + 4 * w + 0][c] = t.x;
                KP[d0 + 4 * w + 1][c] = t.y;
                KP[d0 + 4 * w + 2][c] = t.z;
                KP[d0 + 4 * w + 3][c] = t.w;
                *(float4*)&Vs[c][d0 + 4 * w] = vs[w];
            }
        }
        __syncthreads();

        ull s2[8][2];
#pragma unroll
        for (int i = 0; i < 8; i++) { s2[i][0] = 0ull; s2[i][1] = 0ull; }

#pragma unroll 8
        for (int d = 0; d < 64; d++) {
            float4 qa0 = *(const float4*)&Qs[d][ty * 8];
            float4 qa1 = *(const float4*)&Qs[d][ty * 8 + 4];
            ulonglong2 kb = *(const ulonglong2*)&KP[d][tx * 4];
            ull du[8];
            du[0] = pack2(qa0.x); du[1] = pack2(qa0.y);
            du[2] = pack2(qa0.z); du[3] = pack2(qa0.w);
            du[4] = pack2(qa1.x); du[5] = pack2(qa1.y);
            du[6] = pack2(qa1.z); du[7] = pack2(qa1.w);
#pragma unroll
            for (int i = 0; i < 8; i++) {
                fma2(s2[i][0], du[i], kb.x);
                fma2(s2[i][1], du[i], kb.y);
            }
        }

        float p[8][4];
#pragma unroll
        for (int i = 0; i < 8; i++) {
            float2 u0 = unpack2(s2[i][0]);
            float2 u1 = unpack2(s2[i][1]);
            float t0 = u0.x * SC, t1 = u0.y * SC, t2 = u1.x * SC, t3 = u1.y * SC;
            float rm = fmaxf(fmaxf(t0, t1), fmaxf(t2, t3));
#pragma unroll
            for (int off = 1; off < 16; off <<= 1)
                rm = fmaxf(rm, __shfl_xor_sync(0xFFFFFFFFu, rm, off));
            float nm = fmaxf(m[i], rm);
            float scf = exp2f(m[i] - nm);
            m[i] = nm;
            p[i][0] = exp2f(t0 - nm);
            p[i][1] = exp2f(t1 - nm);
            p[i][2] = exp2f(t2 - nm);
            p[i][3] = exp2f(t3 - nm);
            float rs = (p[i][0] + p[i][1]) + (p[i][2] + p[i][3]);
#pragma unroll
            for (int off = 1; off < 16; off <<= 1)
                rs += __shfl_xor_sync(0xFFFFFFFFu, rs, off);
            l[i] = l[i] * scf + rs;
            ull sd = pack2(scf);
            mul2(acc2[i][0], sd);
            mul2(acc2[i][1], sd);
        }

        __syncthreads();
#pragma unroll
        for (int i = 0; i < 8; i++)
            *(float4*)&KP[ty * 8 + i][tx * 4] =
                make_float4(p[i][0], p[i][1], p[i][2], p[i][3]);
        __syncthreads();

#pragma unroll 4
        for (int c0 = 0; c0 < 64; c0 += 4) {
            float pr[8][4];
#pragma unroll
            for (int i = 0; i < 8; i++)
                *(float4*)pr[i] = *(const float4*)&KP[ty * 8 + i][c0];
            ulonglong2 v0 = *(const ulonglong2*)&Vs[c0 + 0][tx * 4];
            ulonglong2 v1 = *(const ulonglong2*)&Vs[c0 + 1][tx * 4];
            ulonglong2 v2 = *(const ulonglong2*)&Vs[c0 + 2][tx * 4];
            ulonglong2 v3 = *(const ulonglong2*)&Vs[c0 + 3][tx * 4];
#pragma unroll
            for (int i = 0; i < 8; i++) {
                ull pd;
                pd = pack2(pr[i][0]); fma2(acc2[i][0], pd, v0.x); fma2(acc2[i][1], pd, v0.y);
                pd = pack2(pr[i][1]); fma2(acc2[i][0], pd, v1.x); fma2(acc2[i][1], pd, v1.y);
                pd = pack2(pr[i][2]); fma2(acc2[i][0], pd, v2.x); fma2(acc2[i][1], pd, v2.y);
                pd = pack2(pr[i][3]); fma2(acc2[i][0], pd, v3.x); fma2(acc2[i][1], pd, v3.y);
            }
        }
    }

    int b  = hidx >> 4;
    int gh = hidx & 15;
#pragma unroll
    for (int i = 0; i < 8; i++) {
        float inv = 1.f / l[i];
        float2 u0 = unpack2(acc2[i][0]);
        float2 u1 = unpack2(acc2[i][1]);
        float4 o = make_float4(u0.x * inv, u0.y * inv, u1.x * inv, u1.y * inv);
        size_t row = (size_t)b * S_ + (size_t)qt * 64 + ty * 8 + i;
        *(float4*)(ctx + row * H_ + gh * 64 + tx * 4) = o;
    }
}

// ---------------------------------------------------------------------------
extern "C" void kernel_launch(void* const* d_in, const int* in_sizes, int n_in,
                              void* d_out, int out_size)
{
    const float* x  = (const float*)d_in[0];
    const float* Wq = (const float*)d_in[1];
    const float* bq = (const float*)d_in[2];
    const float* Wk = (const float*)d_in[3];
    const float* bk = (const float*)d_in[4];
    const float* Wv = (const float*)d_in[5];
    const float* bv = (const float*)d_in[6];
    const float* Wo = (const float*)d_in[7];
    const float* bo = (const float*)d_in[8];
    float* out = (float*)d_out;

    float *q, *k, *v, *ctx;
    __nv_bfloat16 *ahi, *alo, *whi, *wlo;
    cudaGetSymbolAddress((void**)&q,   g_q);
    cudaGetSymbolAddress((void**)&k,   g_k);
    cudaGetSymbolAddress((void**)&v,   g_v);
    cudaGetSymbolAddress((void**)&ctx, g_ctx);
    cudaGetSymbolAddress((void**)&ahi, g_ahi);
    cudaGetSymbolAddress((void**)&alo, g_alo);
    cudaGetSymbolAddress((void**)&whi, g_whi);
    cudaGetSymbolAddress((void**)&wlo, g_wlo);

    const int NW = H_ * H_;  // 1M elements per weight matrix
    split_kernel<<<(M_ * H_) / 1024, 256>>>(x, ahi, alo, M_ * H_);
    split_kernel<<<NW / 1024, 256>>>(Wq, whi + 0 * NW, wlo + 0 * NW, NW);
    split_kernel<<<NW / 1024, 256>>>(Wk, whi + 1 * NW, wlo + 1 * NW, NW);
    split_kernel<<<NW / 1024, 256>>>(Wv, whi + 2 * NW, wlo + 2 * NW, NW);
    split_kernel<<<NW / 1024, 256>>>(Wo, whi + 3 * NW, wlo + 3 * NW, NW);

    dim3 ggrid(8, 32);   // N/128, M/128
    tc_gemm<<<ggrid, 256>>>(ahi, alo, whi + 0 * NW, wlo + 0 * NW, bq, q, 1);
    tc_gemm<<<ggrid, 256>>>(ahi, alo, whi + 1 * NW, wlo + 1 * NW, bk, k, 1);
    tc_gemm<<<ggrid, 256>>>(ahi, alo, whi + 2 * NW, wlo + 2 * NW, bv, v, 1);

    attn_kernel<<<dim3(S_ / 64, NHEADS), 128>>>(q, k, v, ctx);

    split_kernel<<<(M_ * H_) / 1024, 256>>>(ctx, ahi, alo, M_ * H_);
    tc_gemm<<<ggrid, 256>>>(ahi, alo, whi + 3 * NW, wlo + 3 * NW, bo, out, 0);
}

// round 5
// speedup vs baseline: 5.9096x; 2.0106x over previous
#include <cuda_runtime.h>
#include <cuda_bf16.h>
#include <stdint.h>
#include <math.h>

#define B_    2
#define S_    2048
#define H_    1024
#define G_    4
#define HPG_  4
#define HD_   64
#define M_    (B_ * S_)          // 4096
#define NHEADS (B_ * G_ * HPG_)  // 32

// ---------------- scratch (device globals; no allocation allowed) ----------
__device__ __nv_bfloat16 g_ahi[M_ * H_];     // activation hi (x, later ctx)
__device__ __nv_bfloat16 g_alo[M_ * H_];     // activation lo
__device__ __nv_bfloat16 g_whi[4 * H_ * H_]; // Wq|Wk|Wv|Wo hi
__device__ __nv_bfloat16 g_wlo[4 * H_ * H_]; // lo
__device__ __nv_bfloat16 g_qh[M_ * H_];      // q/k/v split, [hidx][s][hd]
__device__ __nv_bfloat16 g_ql[M_ * H_];
__device__ __nv_bfloat16 g_kh[M_ * H_];
__device__ __nv_bfloat16 g_kl[M_ * H_];
__device__ __nv_bfloat16 g_vh[M_ * H_];
__device__ __nv_bfloat16 g_vl[M_ * H_];

// ---------------- PTX helpers (plain sm_80/90 features only) ----------------
__device__ __forceinline__ uint32_t smem_u32(const void* p) {
    uint32_t a;
    asm("{ .reg .u64 t; cvta.to.shared.u64 t, %1; cvt.u32.u64 %0, t; }" : "=r"(a) : "l"(p));
    return a;
}
__device__ __forceinline__ void cp16(uint32_t dst, const void* src) {
    asm volatile("cp.async.cg.shared.global [%0], [%1], 16;" :: "r"(dst), "l"(src) : "memory");
}
#define CP_COMMIT() asm volatile("cp.async.commit_group;" ::: "memory")
#define LDSM4(r, a) \
    asm volatile("ldmatrix.sync.aligned.m8n8.x4.shared.b16 {%0,%1,%2,%3}, [%4];" \
        : "=r"((r)[0]), "=r"((r)[1]), "=r"((r)[2]), "=r"((r)[3]) : "r"(a))
#define LDSM4T(r, a) \
    asm volatile("ldmatrix.sync.aligned.m8n8.x4.trans.shared.b16 {%0,%1,%2,%3}, [%4];" \
        : "=r"((r)[0]), "=r"((r)[1]), "=r"((r)[2]), "=r"((r)[3]) : "r"(a))
#define MMA_BF16(d, a, b0, b1) \
    asm volatile("mma.sync.aligned.m16n8k16.row.col.f32.bf16.bf16.f32 " \
        "{%0,%1,%2,%3}, {%4,%5,%6,%7}, {%8,%9}, {%0,%1,%2,%3};" \
        : "+f"((d)[0]), "+f"((d)[1]), "+f"((d)[2]), "+f"((d)[3]) \
        : "r"((a)[0]), "r"((a)[1]), "r"((a)[2]), "r"((a)[3]), "r"(b0), "r"(b1))

// pack two f32 -> bf16x2 (lo half = `lo` arg, hi half = `hi` arg)
__device__ __forceinline__ uint32_t packbf(float hi, float lo) {
    uint32_t d;
    asm("cvt.rn.bf16x2.f32 %0, %1, %2;" : "=r"(d) : "f"(hi), "f"(lo));
    return d;
}
__device__ __forceinline__ float bfhi(float x) {
    return __bfloat162float(__float2bfloat16_rn(x));
}

// smem row swizzle: 128B rows, 16B chunk q of row r at r*128 + ((q^(r&7))<<4)
#define SW(r, q) ((uint32_t)(r) * 128u + (uint32_t)((((q) ^ ((r) & 7)) << 4)))

// ---------------------------------------------------------------------------
// split fp32 -> bf16 hi + bf16 lo
// ---------------------------------------------------------------------------
__global__ void __launch_bounds__(256) split_kernel(
    const float* __restrict__ src,
    __nv_bfloat16* __restrict__ hi,
    __nv_bfloat16* __restrict__ lo,
    int n)
{
    int i = (blockIdx.x * 256 + threadIdx.x) * 4;
    if (i >= n) return;
    float4 v = *(const float4*)(src + i);
    float h0 = bfhi(v.x), h1 = bfhi(v.y), h2 = bfhi(v.z), h3 = bfhi(v.w);
    *(uint32_t*)(hi + i)     = packbf(v.y, v.x);
    *(uint32_t*)(hi + i + 2) = packbf(v.w, v.z);
    *(uint32_t*)(lo + i)     = packbf(v.y - h1, v.x - h0);
    *(uint32_t*)(lo + i + 2) = packbf(v.w - h3, v.z - h2);
}

// ---------------------------------------------------------------------------
// HMMA split-bf16 GEMM: C[m,n] = sum_k A[m,k]*W[n,k] + bias[n]
// M=4096, N=1024, K=1024. CTA 128x128, BK=16, 2-stage cp.async pipeline.
// 8 warps (4m x 2n), each 32x64. mode 0: fp32 row-major out.
// mode 1: QKV head remap, split-bf16 out to (Ch, Cl).
// ---------------------------------------------------------------------------
__global__ void __launch_bounds__(256, 1) tc_gemm(
    const __nv_bfloat16* __restrict__ Ahi, const __nv_bfloat16* __restrict__ Alo,
    const __nv_bfloat16* __restrict__ Whi, const __nv_bfloat16* __restrict__ Wlo,
    const float* __restrict__ bias, float* __restrict__ C,
    __nv_bfloat16* __restrict__ Ch, __nv_bfloat16* __restrict__ Cl, int mode)
{
    __shared__ __align__(128) char sm[2][16384];
    const int K = 1024;
    int tid  = threadIdx.x;
    int wid  = tid >> 5, lane = tid & 31;
    int warp_m = wid & 3, warp_n = wid >> 2;
    int bm = blockIdx.y * 128, bn = blockIdx.x * 128;
    uint32_t sbase = smem_u32(sm);

    int lr = tid >> 1, lq = tid & 1;
    uint32_t sw_off = (uint32_t)lr * 32 + (uint32_t)((lq ^ ((lr >> 2) & 1)) << 4);
    const char* gAh = (const char*)(Ahi + (size_t)(bm + lr) * K) + lq * 16;
    const char* gAl = (const char*)(Alo + (size_t)(bm + lr) * K) + lq * 16;
    const char* gWh = (const char*)(Whi + (size_t)(bn + lr) * K) + lq * 16;
    const char* gWl = (const char*)(Wlo + (size_t)(bn + lr) * K) + lq * 16;

#define ISSUE_G(slab) do { \
    uint32_t st_ = sbase + (uint32_t)(((slab) & 1) * 16384); \
    size_t go_ = (size_t)(slab) * 32; \
    cp16(st_ + 0     + sw_off, gAh + go_); \
    cp16(st_ + 4096  + sw_off, gAl + go_); \
    cp16(st_ + 8192  + sw_off, gWh + go_); \
    cp16(st_ + 12288 + sw_off, gWl + go_); \
    CP_COMMIT(); \
} while (0)

    int mat = lane >> 3, l7 = lane & 7;
    int aR = warp_m * 32 + (mat & 1) * 8 + l7;
    int aQ = mat >> 1;
    int bR = warp_n * 64 + (mat >> 1) * 8 + l7;
    int bQ = mat & 1;
    uint32_t aSw = (uint32_t)aR * 32 + (uint32_t)((aQ ^ ((aR >> 2) & 1)) << 4);
    uint32_t bSw = (uint32_t)bR * 32 + (uint32_t)((bQ ^ ((bR >> 2) & 1)) << 4);

    float acc[2][8][4];
#pragma unroll
    for (int mt = 0; mt < 2; mt++)
#pragma unroll
        for (int nt = 0; nt < 8; nt++)
#pragma unroll
            for (int j = 0; j < 4; j++) acc[mt][nt][j] = 0.f;

    ISSUE_G(0);
    for (int c = 0; c < 64; c++) {
        if (c + 1 < 64) {
            ISSUE_G(c + 1);
            asm volatile("cp.async.wait_group 1;" ::: "memory");
        } else {
            asm volatile("cp.async.wait_group 0;" ::: "memory");
        }
        __syncthreads();
        uint32_t st = sbase + (uint32_t)((c & 1) * 16384);

        uint32_t Ah[2][4], Al[2][4], Bh[4][4], Bl[4][4];
        LDSM4(Ah[0], st + aSw);
        LDSM4(Ah[1], st + aSw + 512);
        LDSM4(Al[0], st + 4096 + aSw);
        LDSM4(Al[1], st + 4096 + aSw + 512);
#pragma unroll
        for (int g4 = 0; g4 < 4; g4++) {
            LDSM4(Bh[g4], st + 8192  + bSw + g4 * 512);
            LDSM4(Bl[g4], st + 12288 + bSw + g4 * 512);
        }
#pragma unroll
        for (int mt = 0; mt < 2; mt++)
#pragma unroll
            for (int nt = 0; nt < 8; nt++) {
                uint32_t bh0 = Bh[nt >> 1][(nt & 1) * 2];
                uint32_t bh1 = Bh[nt >> 1][(nt & 1) * 2 + 1];
                uint32_t bl0 = Bl[nt >> 1][(nt & 1) * 2];
                uint32_t bl1 = Bl[nt >> 1][(nt & 1) * 2 + 1];
                MMA_BF16(acc[mt][nt], Ah[mt], bh0, bh1);
                MMA_BF16(acc[mt][nt], Al[mt], bh0, bh1);
                MMA_BF16(acc[mt][nt], Ah[mt], bl0, bl1);
            }
        __syncthreads();
    }
#undef ISSUE_G

    int g = lane >> 2, t = lane & 3;
#pragma unroll
    for (int mt = 0; mt < 2; mt++) {
        int row0 = bm + warp_m * 32 + mt * 16 + g;
#pragma unroll
        for (int nt = 0; nt < 8; nt++) {
            int col = bn + warp_n * 64 + nt * 8 + 2 * t;
            float2 bv = *(const float2*)(bias + col);
            float v0 = acc[mt][nt][0] + bv.x, v1 = acc[mt][nt][1] + bv.y;
            float v2 = acc[mt][nt][2] + bv.x, v3 = acc[mt][nt][3] + bv.y;
            if (mode == 0) {
                *(float2*)(C + (size_t)row0 * H_ + col)       = make_float2(v0, v1);
                *(float2*)(C + (size_t)(row0 + 8) * H_ + col) = make_float2(v2, v3);
            } else {
                int gph = col >> 6, hd0 = col & 63;
                int b0 = row0 >> 11, s0 = row0 & 2047;
                int b1 = (row0 + 8) >> 11, s1 = (row0 + 8) & 2047;
                size_t i0 = (size_t)(b0 * 16 + gph) * (S_ * HD_) + (size_t)s0 * HD_ + hd0;
                size_t i1 = (size_t)(b1 * 16 + gph) * (S_ * HD_) + (size_t)s1 * HD_ + hd0;
                float h0 = bfhi(v0), h1 = bfhi(v1), h2 = bfhi(v2), h3 = bfhi(v3);
                *(uint32_t*)(Ch + i0) = packbf(v1, v0);
                *(uint32_t*)(Cl + i0) = packbf(v1 - h1, v0 - h0);
                *(uint32_t*)(Ch + i1) = packbf(v3, v2);
                *(uint32_t*)(Cl + i1) = packbf(v3 - h3, v2 - h2);
            }
        }
    }
}

// ---------------------------------------------------------------------------
// HMMA split-bf16 flash attention.
// Grid (16 qtiles, 32 heads), 256 threads (8 warps x m16 = 128 q rows/CTA).
// KV tiles of 64 keys; 2-stage cp.async pipeline (32KB/stage, dynamic smem).
// Outputs ctx as split bf16 directly into the Wo GEMM input buffers.
// ---------------------------------------------------------------------------
__global__ void __launch_bounds__(256, 1) attn_mma(
    const __nv_bfloat16* __restrict__ Qh_, const __nv_bfloat16* __restrict__ Ql_,
    const __nv_bfloat16* __restrict__ Kh_, const __nv_bfloat16* __restrict__ Kl_,
    const __nv_bfloat16* __restrict__ Vh_, const __nv_bfloat16* __restrict__ Vl_,
    __nv_bfloat16* __restrict__ Ch, __nv_bfloat16* __restrict__ Cl)
{
    extern __shared__ __align__(128) char smdyn[];   // 2 stages x 32KB
    uint32_t s0 = smem_u32(smdyn);
    uint32_t s1 = s0 + 32768;

    int hidx = blockIdx.y, qt = blockIdx.x;
    int tid = threadIdx.x, warp = tid >> 5, lane = tid & 31;
    int g = lane >> 2, t = lane & 3;
    int mat = lane >> 3, l7 = lane & 7;

    size_t hoff = (size_t)hidx * (S_ * HD_);
    const char* Qhg = (const char*)(Qh_ + hoff + (size_t)qt * 128 * HD_);
    const char* Qlg = (const char*)(Ql_ + hoff + (size_t)qt * 128 * HD_);
    const char* Khg = (const char*)(Kh_ + hoff);
    const char* Klg = (const char*)(Kl_ + hoff);
    const char* Vhg = (const char*)(Vh_ + hoff);
    const char* Vlg = (const char*)(Vl_ + hoff);

    // ---- stage Q (Qh at s0+0, Ql at s0+16K), load fragments, then free ----
    {
        int r = tid >> 1, qb = (tid & 1) * 4;
#pragma unroll
        for (int i = 0; i < 4; i++) {
            cp16(s0 + SW(r, qb + i),         Qhg + (size_t)r * 128 + (qb + i) * 16);
            cp16(s0 + 16384 + SW(r, qb + i), Qlg + (size_t)r * 128 + (qb + i) * 16);
        }
        CP_COMMIT();
        asm volatile("cp.async.wait_group 0;" ::: "memory");
        __syncthreads();
    }
    uint32_t qfh[4][4], qfl[4][4];
    {
        int aRow = warp * 16 + (mat & 1) * 8 + l7;
#pragma unroll
        for (int kc = 0; kc < 4; kc++) {
            int q = kc * 2 + (mat >> 1);
            LDSM4(qfh[kc], s0 + SW(aRow, q));
            LDSM4(qfl[kc], s0 + 16384 + SW(aRow, q));
        }
    }
    __syncthreads();

    // ---- KV pipeline ----
    int kr = tid >> 2, kqb = (tid & 3) * 2;
#define ISSUE_KV(kt) do { \
    uint32_t st_ = ((kt) & 1) ? s1 : s0; \
    size_t ro_ = (size_t)((kt) * 64 + kr) * 128; \
    _Pragma("unroll") \
    for (int j_ = 0; j_ < 2; j_++) { \
        int q_ = kqb + j_; \
        uint32_t sw_ = SW(kr, q_); \
        cp16(st_ + 0     + sw_, Khg + ro_ + q_ * 16); \
        cp16(st_ + 8192  + sw_, Klg + ro_ + q_ * 16); \
        cp16(st_ + 16384 + sw_, Vhg + ro_ + q_ * 16); \
        cp16(st_ + 24576 + sw_, Vlg + ro_ + q_ * 16); \
    } \
    CP_COMMIT(); \
} while (0)

    float oacc[8][4];
#pragma unroll
    for (int j = 0; j < 8; j++)
#pragma unroll
        for (int i = 0; i < 4; i++) oacc[j][i] = 0.f;
    float m0 = -1e30f, m1 = -1e30f, l0 = 0.f, l1 = 0.f;
    const float SC = 0.18033688011112042f;   // (1/sqrt(64)) * log2(e)

    ISSUE_KV(0);
    ISSUE_KV(1);

    for (int kt = 0; kt < 32; kt++) {
        if (kt == 31) asm volatile("cp.async.wait_group 0;" ::: "memory");
        else          asm volatile("cp.async.wait_group 1;" ::: "memory");
        __syncthreads();
        uint32_t st = (kt & 1) ? s1 : s0;

        // ---- scores: S[m16 x 64 keys] ----
        float sacc[8][4];
#pragma unroll
        for (int j = 0; j < 8; j++)
#pragma unroll
            for (int i = 0; i < 4; i++) sacc[j][i] = 0.f;

#pragma unroll
        for (int nc = 0; nc < 4; nc++) {
            uint32_t kfh[4][4], kfl[4][4];
            int bRow = nc * 16 + (mat >> 1) * 8 + l7;
#pragma unroll
            for (int kc = 0; kc < 4; kc++) {
                int q = kc * 2 + (mat & 1);
                LDSM4(kfh[kc], st + SW(bRow, q));
                LDSM4(kfl[kc], st + 8192 + SW(bRow, q));
            }
#pragma unroll
            for (int kc = 0; kc < 4; kc++) {
                MMA_BF16(sacc[2 * nc],     qfh[kc], kfh[kc][0], kfh[kc][1]);
                MMA_BF16(sacc[2 * nc + 1], qfh[kc], kfh[kc][2], kfh[kc][3]);
                MMA_BF16(sacc[2 * nc],     qfl[kc], kfh[kc][0], kfh[kc][1]);
                MMA_BF16(sacc[2 * nc + 1], qfl[kc], kfh[kc][2], kfh[kc][3]);
                MMA_BF16(sacc[2 * nc],     qfh[kc], kfl[kc][0], kfl[kc][1]);
                MMA_BF16(sacc[2 * nc + 1], qfh[kc], kfl[kc][2], kfl[kc][3]);
            }
        }

        // ---- online softmax (rows g and g+8) ----
        float tm0 = -1e30f, tm1 = -1e30f;
#pragma unroll
        for (int j = 0; j < 8; j++) {
            tm0 = fmaxf(tm0, fmaxf(sacc[j][0], sacc[j][1]));
            tm1 = fmaxf(tm1, fmaxf(sacc[j][2], sacc[j][3]));
        }
        tm0 *= SC; tm1 *= SC;
        tm0 = fmaxf(tm0, __shfl_xor_sync(0xFFFFFFFFu, tm0, 1));
        tm0 = fmaxf(tm0, __shfl_xor_sync(0xFFFFFFFFu, tm0, 2));
        tm1 = fmaxf(tm1, __shfl_xor_sync(0xFFFFFFFFu, tm1, 1));
        tm1 = fmaxf(tm1, __shfl_xor_sync(0xFFFFFFFFu, tm1, 2));
        float nm0 = fmaxf(m0, tm0), nm1 = fmaxf(m1, tm1);
        float sc0 = exp2f(m0 - nm0), sc1 = exp2f(m1 - nm1);
        m0 = nm0; m1 = nm1;

        uint32_t pah[4][4], pal[4][4];
        float sum0 = 0.f, sum1 = 0.f;
#pragma unroll
        for (int kc = 0; kc < 4; kc++) {
            int j0 = 2 * kc, j1 = 2 * kc + 1;
            float p00 = exp2f(sacc[j0][0] * SC - nm0);
            float p01 = exp2f(sacc[j0][1] * SC - nm0);
            float p02 = exp2f(sacc[j0][2] * SC - nm1);
            float p03 = exp2f(sacc[j0][3] * SC - nm1);
            float p10 = exp2f(sacc[j1][0] * SC - nm0);
            float p11 = exp2f(sacc[j1][1] * SC - nm0);
            float p12 = exp2f(sacc[j1][2] * SC - nm1);
            float p13 = exp2f(sacc[j1][3] * SC - nm1);
            sum0 += (p00 + p01) + (p10 + p11);
            sum1 += (p02 + p03) + (p12 + p13);
            float h00 = bfhi(p00), h01 = bfhi(p01), h02 = bfhi(p02), h03 = bfhi(p03);
            float h10 = bfhi(p10), h11 = bfhi(p11), h12 = bfhi(p12), h13 = bfhi(p13);
            pah[kc][0] = packbf(p01, p00);
            pah[kc][1] = packbf(p03, p02);
            pah[kc][2] = packbf(p11, p10);
            pah[kc][3] = packbf(p13, p12);
            pal[kc][0] = packbf(p01 - h01, p00 - h00);
            pal[kc][1] = packbf(p03 - h03, p02 - h02);
            pal[kc][2] = packbf(p11 - h11, p10 - h10);
            pal[kc][3] = packbf(p13 - h13, p12 - h12);
        }
        sum0 += __shfl_xor_sync(0xFFFFFFFFu, sum0, 1);
        sum0 += __shfl_xor_sync(0xFFFFFFFFu, sum0, 2);
        sum1 += __shfl_xor_sync(0xFFFFFFFFu, sum1, 1);
        sum1 += __shfl_xor_sync(0xFFFFFFFFu, sum1, 2);
        l0 = l0 * sc0 + sum0;
        l1 = l1 * sc1 + sum1;
#pragma unroll
        for (int j = 0; j < 8; j++) {
            oacc[j][0] *= sc0; oacc[j][1] *= sc0;
            oacc[j][2] *= sc1; oacc[j][3] *= sc1;
        }

        // ---- PV: O += P @ V ----
#pragma unroll
        for (int nc2 = 0; nc2 < 4; nc2++) {
            uint32_t vfh[4][4], vfl[4][4];
#pragma unroll
            for (int kc = 0; kc < 4; kc++) {
                int vRow = kc * 16 + (mat & 1) * 8 + l7;
                int q = nc2 * 2 + (mat >> 1);
                LDSM4T(vfh[kc], st + 16384 + SW(vRow, q));
                LDSM4T(vfl[kc], st + 24576 + SW(vRow, q));
            }
#pragma unroll
            for (int kc = 0; kc < 4; kc++) {
                MMA_BF16(oacc[2 * nc2],     pah[kc], vfh[kc][0], vfh[kc][1]);
                MMA_BF16(oacc[2 * nc2 + 1], pah[kc], vfh[kc][2], vfh[kc][3]);
                MMA_BF16(oacc[2 * nc2],     pal[kc], vfh[kc][0], vfh[kc][1]);
                MMA_BF16(oacc[2 * nc2 + 1], pal[kc], vfh[kc][2], vfh[kc][3]);
                MMA_BF16(oacc[2 * nc2],     pah[kc], vfl[kc][0], vfl[kc][1]);
                MMA_BF16(oacc[2 * nc2 + 1], pah[kc], vfl[kc][2], vfl[kc][3]);
            }
        }
        __syncthreads();
        if (kt + 2 < 32) ISSUE_KV(kt + 2);
    }
#undef ISSUE_KV

    // ---- epilogue: ctx split bf16, [b*S+s][gh*64+hd] ----
    float inv0 = 1.f / l0, inv1 = 1.f / l1;
    int b  = hidx >> 4, gh = hidx & 15;
    int srow = qt * 128 + warp * 16 + g;
    size_t base0 = ((size_t)b * S_ + srow) * H_ + gh * 64 + 2 * t;
    size_t base1 = base0 + 8 * (size_t)H_;
#pragma unroll
    for (int j = 0; j < 8; j++) {
        float v0 = oacc[j][0] * inv0, v1 = oacc[j][1] * inv0;
        float v2 = oacc[j][2] * inv1, v3 = oacc[j][3] * inv1;
        float h0 = bfhi(v0), h1 = bfhi(v1), h2 = bfhi(v2), h3 = bfhi(v3);
        *(uint32_t*)(Ch + base0 + j * 8) = packbf(v1, v0);
        *(uint32_t*)(Cl + base0 + j * 8) = packbf(v1 - h1, v0 - h0);
        *(uint32_t*)(Ch + base1 + j * 8) = packbf(v3, v2);
        *(uint32_t*)(Cl + base1 + j * 8) = packbf(v3 - h3, v2 - h2);
    }
}

// ---------------------------------------------------------------------------
extern "C" void kernel_launch(void* const* d_in, const int* in_sizes, int n_in,
                              void* d_out, int out_size)
{
    const float* x  = (const float*)d_in[0];
    const float* Wq = (const float*)d_in[1];
    const float* bq = (const float*)d_in[2];
    const float* Wk = (const float*)d_in[3];
    const float* bk = (const float*)d_in[4];
    const float* Wv = (const float*)d_in[5];
    const float* bv = (const float*)d_in[6];
    const float* Wo = (const float*)d_in[7];
    const float* bo = (const float*)d_in[8];
    float* out = (float*)d_out;

    __nv_bfloat16 *ahi, *alo, *whi, *wlo, *qh, *ql, *kh, *kl, *vh, *vl;
    cudaGetSymbolAddress((void**)&ahi, g_ahi);
    cudaGetSymbolAddress((void**)&alo, g_alo);
    cudaGetSymbolAddress((void**)&whi, g_whi);
    cudaGetSymbolAddress((void**)&wlo, g_wlo);
    cudaGetSymbolAddress((void**)&qh,  g_qh);
    cudaGetSymbolAddress((void**)&ql,  g_ql);
    cudaGetSymbolAddress((void**)&kh,  g_kh);
    cudaGetSymbolAddress((void**)&kl,  g_kl);
    cudaGetSymbolAddress((void**)&vh,  g_vh);
    cudaGetSymbolAddress((void**)&vl,  g_vl);

    cudaFuncSetAttribute(attn_mma, cudaFuncAttributeMaxDynamicSharedMemorySize, 65536);

    const int NW = H_ * H_;
    split_kernel<<<(M_ * H_) / 1024, 256>>>(x, ahi, alo, M_ * H_);
    split_kernel<<<NW / 1024, 256>>>(Wq, whi + 0 * NW, wlo + 0 * NW, NW);
    split_kernel<<<NW / 1024, 256>>>(Wk, whi + 1 * NW, wlo + 1 * NW, NW);
    split_kernel<<<NW / 1024, 256>>>(Wv, whi + 2 * NW, wlo + 2 * NW, NW);
    split_kernel<<<NW / 1024, 256>>>(Wo, whi + 3 * NW, wlo + 3 * NW, NW);

    dim3 ggrid(8, 32);   // N/128, M/128
    tc_gemm<<<ggrid, 256>>>(ahi, alo, whi + 0 * NW, wlo + 0 * NW, bq, nullptr, qh, ql, 1);
    tc_gemm<<<ggrid, 256>>>(ahi, alo, whi + 1 * NW, wlo + 1 * NW, bk, nullptr, kh, kl, 1);
    tc_gemm<<<ggrid, 256>>>(ahi, alo, whi + 2 * NW, wlo + 2 * NW, bv, nullptr, vh, vl, 1);

    // attention writes ctx split directly into ahi/alo (x no longer needed)
    attn_mma<<<dim3(16, 32), 256, 65536>>>(qh, ql, kh, kl, vh, vl, ahi, alo);

    tc_gemm<<<ggrid, 256>>>(ahi, alo, whi + 3 * NW, wlo + 3 * NW, bo, out, nullptr, nullptr, 0);
}